// round 1
// baseline (speedup 1.0000x reference)
#include <cuda_runtime.h>
#include <cuda_bf16.h>
#include <cstdint>

// Problem constants (fixed shapes)
#define BATCH 2
#define SEQ   2048
#define DMODEL 2048
#define NH    32
#define NKV   8
#define HD    64
#define NTOK  (BATCH*SEQ)          // 4096
#define KINT  (DMODEL/4)           // 512 ints per row

// ---------------- device scratch (static, allocation-free) ----------------
__device__ float g_partial[4*256];
__device__ float g_wscale[4];
__device__ signed char g_wq[DMODEL*DMODEL];
__device__ signed char g_wk[NKV*HD*DMODEL];
__device__ signed char g_wv[NKV*HD*DMODEL];
__device__ signed char g_wo[DMODEL*DMODEL];
__device__ signed char g_xq0[NTOK*DMODEL];
__device__ signed char g_xq1[NTOK*DMODEL];
__device__ signed char g_xq2[NTOK*DMODEL];
__device__ signed char g_xqo[NTOK*DMODEL];
__device__ float g_xs0[NTOK];
__device__ float g_xs1[NTOK];
__device__ float g_xs2[NTOK];
__device__ float g_xso[NTOK];
__device__ float g_projq[NTOK*DMODEL];     // [token, h*64+d]
__device__ float g_projk[NTOK*NKV*HD];     // [token, kv*64+d]
__device__ float g_projv[NTOK*NKV*HD];
__device__ float g_attn[NTOK*DMODEL];      // [token, h*64+d]

// ---------------- weight abs-mean (deterministic 2-pass) ----------------
__global__ void absum_partial(const float* __restrict__ w, int n, int k) {
    __shared__ float red[256];
    int tid = threadIdx.x;
    float s = 0.f;
    for (int i = blockIdx.x*256 + tid; i < n; i += 256*256) s += fabsf(w[i]);
    red[tid] = s; __syncthreads();
    for (int st = 128; st > 0; st >>= 1) { if (tid < st) red[tid] += red[tid+st]; __syncthreads(); }
    if (tid == 0) g_partial[k*256 + blockIdx.x] = red[0];
}

__global__ void finalize_wscale() {
    __shared__ float red[256];
    int tid = threadIdx.x;
    const float ninv[4] = {1.f/(2048.f*2048.f), 1.f/(512.f*2048.f),
                           1.f/(512.f*2048.f), 1.f/(2048.f*2048.f)};
    for (int k = 0; k < 4; k++) {
        red[tid] = g_partial[k*256 + tid]; __syncthreads();
        for (int st = 128; st > 0; st >>= 1) { if (tid < st) red[tid] += red[tid+st]; __syncthreads(); }
        if (tid == 0) g_wscale[k] = fmaxf(red[0]*ninv[k], 1e-5f);
        __syncthreads();
    }
}

__global__ void quant_w(const float* __restrict__ w, signed char* __restrict__ wq, int n, int widx) {
    float inv = 1.f / g_wscale[widx];
    for (int i = blockIdx.x*blockDim.x + threadIdx.x; i < n; i += gridDim.x*blockDim.x) {
        float q = rintf(w[i]*inv);
        q = fminf(fmaxf(q, -1.f), 1.f);
        wq[i] = (signed char)q;
    }
}

// ---------------- activation quant (rmsnorm + absmax int8), up to 3 g's ----------------
__global__ void act_quant(const float* __restrict__ x,
                          const float* g0, const float* g1, const float* g2,
                          signed char* xq0, signed char* xq1, signed char* xq2,
                          float* s0, float* s1, float* s2) {
    __shared__ float xr[DMODEL];
    __shared__ float red[256];
    int row = blockIdx.x, tid = threadIdx.x;
    const float* xp = x + (size_t)row*DMODEL;
    float ss = 0.f;
    #pragma unroll
    for (int l = 0; l < 8; l++) { float v = xp[tid + l*256]; xr[tid + l*256] = v; ss += v*v; }
    red[tid] = ss; __syncthreads();
    for (int st = 128; st > 0; st >>= 1) { if (tid < st) red[tid] += red[tid+st]; __syncthreads(); }
    float rinv = rsqrtf(red[0]*(1.f/(float)DMODEL) + 1e-6f);
    __syncthreads();

    const float* gs[3] = {g0, g1, g2};
    signed char* xqs[3] = {xq0, xq1, xq2};
    float* scs[3] = {s0, s1, s2};
    for (int vI = 0; vI < 3; vI++) {
        const float* g = gs[vI];
        if (!g) continue;
        float amax = 0.f, xn[8];
        #pragma unroll
        for (int l = 0; l < 8; l++) {
            int i = tid + l*256;
            float v = xr[i]*rinv*g[i];
            xn[l] = v; amax = fmaxf(amax, fabsf(v));
        }
        red[tid] = amax; __syncthreads();
        for (int st = 128; st > 0; st >>= 1) { if (tid < st) red[tid] = fmaxf(red[tid], red[tid+st]); __syncthreads(); }
        float sc = fmaxf(red[0], 1e-5f);
        __syncthreads();
        float qf = 127.f/sc;
        #pragma unroll
        for (int l = 0; l < 8; l++) {
            int i = tid + l*256;
            float q = rintf(xn[l]*qf);
            q = fminf(fmaxf(q, -128.f), 127.f);
            xqs[vI][(size_t)row*DMODEL + i] = (signed char)q;
        }
        if (tid == 0) scs[vI][row] = sc;
    }
}

// ---------------- int8 dp4a GEMM:  C[M,N] = A[M,K] * B[N,K]^T, scaled ----------------
// grid: (N/64, M/64); block: (16,16). smem tiles transposed for LDS.128.
__global__ void gemm_i8(const signed char* __restrict__ A, const signed char* __restrict__ B,
                        const float* __restrict__ xsc, int widx,
                        float* __restrict__ C, int N) {
    __shared__ int As[16][68];
    __shared__ int Bs[16][68];
    int tx = threadIdx.x, ty = threadIdx.y;
    int tid = ty*16 + tx;
    int m0 = blockIdx.y*64, n0 = blockIdx.x*64;
    const int* A4 = (const int*)A;
    const int* B4 = (const int*)B;
    int acc[4][4];
    #pragma unroll
    for (int i = 0; i < 4; i++)
        #pragma unroll
        for (int j = 0; j < 4; j++) acc[i][j] = 0;

    for (int kb = 0; kb < KINT/16; kb++) {
        #pragma unroll
        for (int l = 0; l < 4; l++) {
            int idx = tid + l*256;
            int r = idx >> 4, c = idx & 15;
            As[c][r] = A4[(size_t)(m0 + r)*KINT + kb*16 + c];
            Bs[c][r] = B4[(size_t)(n0 + r)*KINT + kb*16 + c];
        }
        __syncthreads();
        #pragma unroll
        for (int kk = 0; kk < 16; kk++) {
            int4 a = *(const int4*)&As[kk][ty*4];
            int4 b = *(const int4*)&Bs[kk][tx*4];
            int av[4] = {a.x, a.y, a.z, a.w};
            int bv[4] = {b.x, b.y, b.z, b.w};
            #pragma unroll
            for (int i = 0; i < 4; i++)
                #pragma unroll
                for (int j = 0; j < 4; j++)
                    acc[i][j] = __dp4a(av[i], bv[j], acc[i][j]);
        }
        __syncthreads();
    }
    float wsc = g_wscale[widx] * (1.f/127.f);
    #pragma unroll
    for (int i = 0; i < 4; i++) {
        int row = m0 + ty*4 + i;
        float sc = wsc * xsc[row];
        float4 o;
        o.x = acc[i][0]*sc; o.y = acc[i][1]*sc; o.z = acc[i][2]*sc; o.w = acc[i][3]*sc;
        *(float4*)&C[(size_t)row*N + n0 + tx*4] = o;
    }
}

// ---------------- RoPE (in place), layout [token, h*64+d] ----------------
__global__ void rope_kernel(float* __restrict__ buf, const float* __restrict__ cs,
                            const float* __restrict__ sn, int nh) {
    int idx = blockIdx.x*blockDim.x + threadIdx.x;   // over NTOK*nh*32
    int i = idx & 31;
    int h = (idx >> 5) % nh;
    int tok = (idx >> 5) / nh;
    int t = tok & (SEQ - 1);
    float* p = buf + (size_t)tok*(nh*HD) + h*HD;
    float c0 = cs[t*HD + i],      s0 = sn[t*HD + i];
    float c1 = cs[t*HD + 32 + i], s1 = sn[t*HD + 32 + i];
    float a = p[i], b = p[32 + i];
    p[i]      = a*c0 - b*s0;
    p[32 + i] = b*c1 + a*s1;
}

// ---------------- causal flash attention, GQA (n_rep=4) ----------------
// grid: (T/64, NH, B); block 256; dyn smem = (2*64*65 + 64*65) floats = 49920B
__global__ void attn_kernel(const float* __restrict__ Q, const float* __restrict__ K,
                            const float* __restrict__ V, float* __restrict__ O) {
    extern __shared__ float sm[];
    float* qs = sm;               // [64][65]
    float* ks = sm + 64*65;       // [64][65]  (reused for V)
    float* ps = sm + 2*64*65;     // [64][65]
    int tid = threadIdx.x;
    int qt = blockIdx.x, h = blockIdx.y, b = blockIdx.z;
    int q0 = qt*64, kvh = h >> 2;
    const float* Qb = Q + (size_t)(b*SEQ)*DMODEL + h*HD;
    const float* Kb = K + (size_t)(b*SEQ)*(NKV*HD) + kvh*HD;
    const float* Vb = V + (size_t)(b*SEQ)*(NKV*HD) + kvh*HD;

    #pragma unroll
    for (int l = 0; l < 16; l++) {
        int idx = tid + l*256; int r = idx >> 6, d = idx & 63;
        qs[r*65 + d] = Qb[(size_t)(q0 + r)*DMODEL + d];
    }
    int row = tid >> 2, c4 = tid & 3;
    float m_i = -1e30f, l_i = 0.f, o[16];
    #pragma unroll
    for (int dd = 0; dd < 16; dd++) o[dd] = 0.f;

    for (int kt = 0; kt <= qt; kt++) {
        int j0 = kt*64;
        __syncthreads();   // prior PV done before overwriting ks
        #pragma unroll
        for (int l = 0; l < 16; l++) {
            int idx = tid + l*256; int r = idx >> 6, d = idx & 63;
            ks[r*65 + d] = Kb[(size_t)(j0 + r)*(NKV*HD) + d];
        }
        __syncthreads();
        float s[16];
        #pragma unroll
        for (int jj = 0; jj < 16; jj++) s[jj] = 0.f;
        for (int d = 0; d < 64; d++) {
            float qv = qs[row*65 + d];
            #pragma unroll
            for (int jj = 0; jj < 16; jj++)
                s[jj] += qv * ks[(c4*16 + jj)*65 + d];
        }
        float tm = -1e30f;
        #pragma unroll
        for (int jj = 0; jj < 16; jj++) {
            int jg = j0 + c4*16 + jj;
            s[jj] = (jg <= q0 + row) ? s[jj]*0.125f : -1e30f;
            tm = fmaxf(tm, s[jj]);
        }
        tm = fmaxf(tm, __shfl_xor_sync(0xffffffffu, tm, 1));
        tm = fmaxf(tm, __shfl_xor_sync(0xffffffffu, tm, 2));
        float nm = fmaxf(m_i, tm);
        float corr = __expf(m_i - nm);
        float ts = 0.f;
        #pragma unroll
        for (int jj = 0; jj < 16; jj++) { float p = __expf(s[jj] - nm); s[jj] = p; ts += p; }
        ts += __shfl_xor_sync(0xffffffffu, ts, 1);
        ts += __shfl_xor_sync(0xffffffffu, ts, 2);
        l_i = l_i*corr + ts; m_i = nm;
        #pragma unroll
        for (int dd = 0; dd < 16; dd++) o[dd] *= corr;
        #pragma unroll
        for (int jj = 0; jj < 16; jj++) ps[row*65 + c4*16 + jj] = s[jj];
        __syncthreads();
        #pragma unroll
        for (int l = 0; l < 16; l++) {
            int idx = tid + l*256; int r = idx >> 6, d = idx & 63;
            ks[r*65 + d] = Vb[(size_t)(j0 + r)*(NKV*HD) + d];
        }
        __syncthreads();
        for (int j = 0; j < 64; j++) {
            float pv = ps[row*65 + j];
            #pragma unroll
            for (int dd = 0; dd < 16; dd++)
                o[dd] += pv * ks[j*65 + c4*16 + dd];
        }
    }
    float inv = 1.f / l_i;
    float* Ob = O + (size_t)(b*SEQ)*DMODEL + h*HD;
    #pragma unroll
    for (int dd = 0; dd < 16; dd++)
        Ob[(size_t)(q0 + row)*DMODEL + c4*16 + dd] = o[dd]*inv;
}

// ---------------- launch ----------------
extern "C" void kernel_launch(void* const* d_in, const int* in_sizes, int n_in,
                              void* d_out, int out_size) {
    const float* x   = (const float*)d_in[0];
    const float* cs  = (const float*)d_in[1];
    const float* sn  = (const float*)d_in[2];
    const float* wq  = (const float*)d_in[3];
    const float* wk  = (const float*)d_in[4];
    const float* wv  = (const float*)d_in[5];
    const float* wo  = (const float*)d_in[6];
    const float* gq  = (const float*)d_in[7];
    const float* gk  = (const float*)d_in[8];
    const float* gv  = (const float*)d_in[9];
    const float* go  = (const float*)d_in[10];
    float* out = (float*)d_out;

    signed char *wq_q, *wk_q, *wv_q, *wo_q, *xq0, *xq1, *xq2, *xqo;
    float *xs0, *xs1, *xs2, *xso, *projq, *projk, *projv, *attnb;
    cudaGetSymbolAddress((void**)&wq_q, g_wq);
    cudaGetSymbolAddress((void**)&wk_q, g_wk);
    cudaGetSymbolAddress((void**)&wv_q, g_wv);
    cudaGetSymbolAddress((void**)&wo_q, g_wo);
    cudaGetSymbolAddress((void**)&xq0, g_xq0);
    cudaGetSymbolAddress((void**)&xq1, g_xq1);
    cudaGetSymbolAddress((void**)&xq2, g_xq2);
    cudaGetSymbolAddress((void**)&xqo, g_xqo);
    cudaGetSymbolAddress((void**)&xs0, g_xs0);
    cudaGetSymbolAddress((void**)&xs1, g_xs1);
    cudaGetSymbolAddress((void**)&xs2, g_xs2);
    cudaGetSymbolAddress((void**)&xso, g_xso);
    cudaGetSymbolAddress((void**)&projq, g_projq);
    cudaGetSymbolAddress((void**)&projk, g_projk);
    cudaGetSymbolAddress((void**)&projv, g_projv);
    cudaGetSymbolAddress((void**)&attnb, g_attn);

    cudaFuncSetAttribute(attn_kernel, cudaFuncAttributeMaxDynamicSharedMemorySize, 49920);

    // weight scales + ternary quant
    absum_partial<<<256, 256>>>(wq, DMODEL*DMODEL, 0);
    absum_partial<<<256, 256>>>(wk, NKV*HD*DMODEL, 1);
    absum_partial<<<256, 256>>>(wv, NKV*HD*DMODEL, 2);
    absum_partial<<<256, 256>>>(wo, DMODEL*DMODEL, 3);
    finalize_wscale<<<1, 256>>>();
    quant_w<<<2048, 256>>>(wq, wq_q, DMODEL*DMODEL, 0);
    quant_w<<<512, 256>>>(wk, wk_q, NKV*HD*DMODEL, 1);
    quant_w<<<512, 256>>>(wv, wv_q, NKV*HD*DMODEL, 2);
    quant_w<<<2048, 256>>>(wo, wo_q, DMODEL*DMODEL, 3);

    // activation quant (3 projections share x row + rmsnorm stat)
    act_quant<<<NTOK, 256>>>(x, gq, gk, gv, xq0, xq1, xq2, xs0, xs1, xs2);

    // projections
    gemm_i8<<<dim3(DMODEL/64, NTOK/64), dim3(16, 16)>>>(xq0, wq_q, xs0, 0, projq, DMODEL);
    gemm_i8<<<dim3((NKV*HD)/64, NTOK/64), dim3(16, 16)>>>(xq1, wk_q, xs1, 1, projk, NKV*HD);
    gemm_i8<<<dim3((NKV*HD)/64, NTOK/64), dim3(16, 16)>>>(xq2, wv_q, xs2, 2, projv, NKV*HD);

    // rope
    rope_kernel<<<(NTOK*NH*32)/256, 256>>>(projq, cs, sn, NH);
    rope_kernel<<<(NTOK*NKV*32)/256, 256>>>(projk, cs, sn, NKV);

    // attention
    attn_kernel<<<dim3(SEQ/64, NH, BATCH), 256, 49920>>>(projq, projk, projv, attnb);

    // output bitlinear
    act_quant<<<NTOK, 256>>>(attnb, go, nullptr, nullptr, xqo, nullptr, nullptr, xso, nullptr, nullptr);
    gemm_i8<<<dim3(DMODEL/64, NTOK/64), dim3(16, 16)>>>(xqo, wo_q, xso, 3, out, DMODEL);
}

// round 2
// speedup vs baseline: 2.8508x; 2.8508x over previous
#include <cuda_runtime.h>
#include <cuda_bf16.h>
#include <cstdint>

// Problem constants (fixed shapes)
#define BATCH 2
#define SEQ   2048
#define DMODEL 2048
#define NH    32
#define NKV   8
#define HD    64
#define NTOK  (BATCH*SEQ)          // 4096
#define KINT  (DMODEL/4)           // 512 ints per row

// ---------------- f32x2 packed math helpers ----------------
__device__ __forceinline__ void fma2(unsigned long long &d, unsigned long long a, unsigned long long b) {
    asm("fma.rn.f32x2 %0, %1, %2, %0;" : "+l"(d) : "l"(a), "l"(b));
}
__device__ __forceinline__ unsigned long long mul2(unsigned long long a, unsigned long long b) {
    unsigned long long r;
    asm("mul.rn.f32x2 %0, %1, %2;" : "=l"(r) : "l"(a), "l"(b));
    return r;
}
__device__ __forceinline__ unsigned long long pack2(float lo, float hi) {
    unsigned long long r;
    asm("mov.b64 %0, {%1, %2};" : "=l"(r) : "f"(lo), "f"(hi));
    return r;
}
__device__ __forceinline__ void unpack2(unsigned long long v, float &lo, float &hi) {
    asm("mov.b64 {%0, %1}, %2;" : "=f"(lo), "=f"(hi) : "l"(v));
}

// ---------------- device scratch (static, allocation-free) ----------------
__device__ float g_partial[4*256];
__device__ float g_wscale[4];
__device__ signed char g_wq[DMODEL*DMODEL];
__device__ signed char g_wk[NKV*HD*DMODEL];
__device__ signed char g_wv[NKV*HD*DMODEL];
__device__ signed char g_wo[DMODEL*DMODEL];
__device__ signed char g_xq0[NTOK*DMODEL];
__device__ signed char g_xq1[NTOK*DMODEL];
__device__ signed char g_xq2[NTOK*DMODEL];
__device__ signed char g_xqo[NTOK*DMODEL];
__device__ float g_xs0[NTOK];
__device__ float g_xs1[NTOK];
__device__ float g_xs2[NTOK];
__device__ float g_xso[NTOK];
__device__ float g_projq[NTOK*DMODEL];     // [token, h*64+d]
__device__ float g_projk[NTOK*NKV*HD];     // [token, kv*64+d]
__device__ float g_projv[NTOK*NKV*HD];
__device__ float g_attn[NTOK*DMODEL];      // [token, h*64+d]

// ---------------- weight abs-mean (deterministic 2-pass) ----------------
__global__ void absum_partial(const float* __restrict__ w, int n, int k) {
    __shared__ float red[256];
    int tid = threadIdx.x;
    float s = 0.f;
    for (int i = blockIdx.x*256 + tid; i < n; i += 256*256) s += fabsf(w[i]);
    red[tid] = s; __syncthreads();
    for (int st = 128; st > 0; st >>= 1) { if (tid < st) red[tid] += red[tid+st]; __syncthreads(); }
    if (tid == 0) g_partial[k*256 + blockIdx.x] = red[0];
}

__global__ void finalize_wscale() {
    __shared__ float red[256];
    int tid = threadIdx.x;
    const float ninv[4] = {1.f/(2048.f*2048.f), 1.f/(512.f*2048.f),
                           1.f/(512.f*2048.f), 1.f/(2048.f*2048.f)};
    for (int k = 0; k < 4; k++) {
        red[tid] = g_partial[k*256 + tid]; __syncthreads();
        for (int st = 128; st > 0; st >>= 1) { if (tid < st) red[tid] += red[tid+st]; __syncthreads(); }
        if (tid == 0) g_wscale[k] = fmaxf(red[0]*ninv[k], 1e-5f);
        __syncthreads();
    }
}

__global__ void quant_w(const float* __restrict__ w, signed char* __restrict__ wq, int n, int widx) {
    float inv = 1.f / g_wscale[widx];
    for (int i = blockIdx.x*blockDim.x + threadIdx.x; i < n; i += gridDim.x*blockDim.x) {
        float q = rintf(w[i]*inv);
        q = fminf(fmaxf(q, -1.f), 1.f);
        wq[i] = (signed char)q;
    }
}

// ---------------- activation quant (rmsnorm + absmax int8), up to 3 g's ----------------
__global__ void act_quant(const float* __restrict__ x,
                          const float* g0, const float* g1, const float* g2,
                          signed char* xq0, signed char* xq1, signed char* xq2,
                          float* s0, float* s1, float* s2) {
    __shared__ float xr[DMODEL];
    __shared__ float red[256];
    int row = blockIdx.x, tid = threadIdx.x;
    const float* xp = x + (size_t)row*DMODEL;
    float ss = 0.f;
    #pragma unroll
    for (int l = 0; l < 8; l++) { float v = xp[tid + l*256]; xr[tid + l*256] = v; ss += v*v; }
    red[tid] = ss; __syncthreads();
    for (int st = 128; st > 0; st >>= 1) { if (tid < st) red[tid] += red[tid+st]; __syncthreads(); }
    float rinv = rsqrtf(red[0]*(1.f/(float)DMODEL) + 1e-6f);
    __syncthreads();

    const float* gs[3] = {g0, g1, g2};
    signed char* xqs[3] = {xq0, xq1, xq2};
    float* scs[3] = {s0, s1, s2};
    for (int vI = 0; vI < 3; vI++) {
        const float* g = gs[vI];
        if (!g) continue;
        float amax = 0.f, xn[8];
        #pragma unroll
        for (int l = 0; l < 8; l++) {
            int i = tid + l*256;
            float v = xr[i]*rinv*g[i];
            xn[l] = v; amax = fmaxf(amax, fabsf(v));
        }
        red[tid] = amax; __syncthreads();
        for (int st = 128; st > 0; st >>= 1) { if (tid < st) red[tid] = fmaxf(red[tid], red[tid+st]); __syncthreads(); }
        float sc = fmaxf(red[0], 1e-5f);
        __syncthreads();
        float qf = 127.f/sc;
        #pragma unroll
        for (int l = 0; l < 8; l++) {
            int i = tid + l*256;
            float q = rintf(xn[l]*qf);
            q = fminf(fmaxf(q, -128.f), 127.f);
            xqs[vI][(size_t)row*DMODEL + i] = (signed char)q;
        }
        if (tid == 0) scs[vI][row] = sc;
    }
}

// ---------------- int8 dp4a GEMM:  C[M,N] = A[M,K]*B[N,K]^T, 128x64 tile, 8x4/thread ----------------
__global__ __launch_bounds__(256)
void gemm_i8(const signed char* __restrict__ A, const signed char* __restrict__ B,
             const float* __restrict__ xsc, int widx,
             float* __restrict__ C, int N) {
    __shared__ int As[16][132];   // [k-int][m-row]
    __shared__ int Bs[16][68];    // [k-int][n-row]
    int tid = threadIdx.x;
    int tx = tid & 15, ty = tid >> 4;
    int m0 = blockIdx.y*128, n0 = blockIdx.x*64;
    const int* A4 = (const int*)A;
    const int* B4 = (const int*)B;
    int acc[8][4];
    #pragma unroll
    for (int i = 0; i < 8; i++)
        #pragma unroll
        for (int j = 0; j < 4; j++) acc[i][j] = 0;

    for (int kb = 0; kb < KINT/16; kb++) {
        #pragma unroll
        for (int l = 0; l < 8; l++) {
            int idx = tid + l*256;   // 0..2047
            int r = idx >> 4, c = idx & 15;
            As[c][r] = A4[(size_t)(m0 + r)*KINT + kb*16 + c];
        }
        #pragma unroll
        for (int l = 0; l < 4; l++) {
            int idx = tid + l*256;   // 0..1023
            int r = idx >> 4, c = idx & 15;
            Bs[c][r] = B4[(size_t)(n0 + r)*KINT + kb*16 + c];
        }
        __syncthreads();
        #pragma unroll
        for (int kk = 0; kk < 16; kk++) {
            int4 a0 = *(const int4*)&As[kk][ty*8];
            int4 a1 = *(const int4*)&As[kk][ty*8 + 4];
            int4 bb = *(const int4*)&Bs[kk][tx*4];
            int av[8] = {a0.x, a0.y, a0.z, a0.w, a1.x, a1.y, a1.z, a1.w};
            int bv[4] = {bb.x, bb.y, bb.z, bb.w};
            #pragma unroll
            for (int i = 0; i < 8; i++)
                #pragma unroll
                for (int j = 0; j < 4; j++)
                    acc[i][j] = __dp4a(av[i], bv[j], acc[i][j]);
        }
        __syncthreads();
    }
    float wsc = g_wscale[widx] * (1.f/127.f);
    #pragma unroll
    for (int i = 0; i < 8; i++) {
        int row = m0 + ty*8 + i;
        float s = wsc * xsc[row];
        float4 o;
        o.x = acc[i][0]*s; o.y = acc[i][1]*s; o.z = acc[i][2]*s; o.w = acc[i][3]*s;
        *(float4*)&C[(size_t)row*N + n0 + tx*4] = o;
    }
}

// ---------------- RoPE (in place), layout [token, h*64+d] ----------------
__global__ void rope_kernel(float* __restrict__ buf, const float* __restrict__ cs,
                            const float* __restrict__ sn, int nh) {
    int idx = blockIdx.x*blockDim.x + threadIdx.x;   // over NTOK*nh*32
    int i = idx & 31;
    int h = (idx >> 5) % nh;
    int tok = (idx >> 5) / nh;
    int t = tok & (SEQ - 1);
    float* p = buf + (size_t)tok*(nh*HD) + h*HD;
    float c0 = cs[t*HD + i],      s0 = sn[t*HD + i];
    float c1 = cs[t*HD + 32 + i], s1 = sn[t*HD + 32 + i];
    float a = p[i], b = p[32 + i];
    p[i]      = a*c0 - b*s0;
    p[32 + i] = b*c1 + a*s1;
}

// ---------------- causal flash attention, GQA (n_rep=4), f32x2 register-tiled ----------------
// grid (SEQ/128, NH, B); 256 threads; dyn smem = 102400 B; 2 CTA/SM
__global__ __launch_bounds__(256, 2)
void attn_kernel(const float* __restrict__ Q, const float* __restrict__ K,
                 const float* __restrict__ V, float* __restrict__ O) {
    extern __shared__ float sm[];
    float* qT  = sm;                   // [64][132]  d-major: qT[d][i], i 0..127
    float* kT  = sm + 64*132;          // [64][68]   d-major: kT[d][j], j 0..63
    float* vs  = kT + 64*68;           // [64][68]   row-major: vs[j][d]
    float* psT = vs + 64*68;           // [64][132]  j-major: psT[j][i]
    int tid = threadIdx.x;
    int qt = blockIdx.x, h = blockIdx.y, b = blockIdx.z;
    int q0 = qt*128, kvh = h >> 2;
    int tx = tid & 15, ty = tid >> 4;
    const float* Qb = Q + (size_t)(b*SEQ + q0)*DMODEL + h*HD;
    const float* Kb = K + (size_t)(b*SEQ)*(NKV*HD) + kvh*HD;
    const float* Vb = V + (size_t)(b*SEQ)*(NKV*HD) + kvh*HD;

    // load Q tile transposed (128 rows x 64 d -> qT[d][i])
    #pragma unroll
    for (int l = 0; l < 8; l++) {
        int idx = tid + l*256;            // 0..2047
        int r = idx >> 4, c4 = idx & 15;
        float4 f = *(const float4*)&Qb[(size_t)r*DMODEL + c4*4];
        qT[(c4*4+0)*132 + r] = f.x;
        qT[(c4*4+1)*132 + r] = f.y;
        qT[(c4*4+2)*132 + r] = f.z;
        qT[(c4*4+3)*132 + r] = f.w;
    }

    float m_i[8], l_i[8];
    unsigned long long o2[4][4];          // [row-pair][dd], rows (ty*8+2a, ty*8+2a+1)
    #pragma unroll
    for (int i = 0; i < 8; i++) { m_i[i] = -1e30f; l_i[i] = 0.f; }
    #pragma unroll
    for (int a = 0; a < 4; a++)
        #pragma unroll
        for (int d = 0; d < 4; d++) o2[a][d] = 0ull;

    int ktmax = 2*qt + 1;
    for (int kt = 0; kt <= ktmax; kt++) {
        int j0 = kt*64;
        __syncthreads();   // previous PV done before overwriting kT/vs
        // load K transposed + V straight (64 x 64 each)
        #pragma unroll
        for (int l = 0; l < 4; l++) {
            int idx = tid + l*256;        // 0..1023
            int r = idx >> 4, c4 = idx & 15;
            float4 f = *(const float4*)&Kb[(size_t)(j0 + r)*(NKV*HD) + c4*4];
            kT[(c4*4+0)*68 + r] = f.x;
            kT[(c4*4+1)*68 + r] = f.y;
            kT[(c4*4+2)*68 + r] = f.z;
            kT[(c4*4+3)*68 + r] = f.w;
            float4 g = *(const float4*)&Vb[(size_t)(j0 + r)*(NKV*HD) + c4*4];
            *(float4*)&vs[r*68 + c4*4] = g;
        }
        __syncthreads();

        // ---- S = Q @ K^T : s2[row-pair a][jj] over d ----
        unsigned long long s2[4][4];
        #pragma unroll
        for (int a = 0; a < 4; a++)
            #pragma unroll
            for (int j = 0; j < 4; j++) s2[a][j] = 0ull;

        #pragma unroll 4
        for (int d = 0; d < 64; d++) {
            ulonglong2 qa = *(const ulonglong2*)&qT[d*132 + ty*8];       // row pairs (0,1),(2,3)
            ulonglong2 qb2 = *(const ulonglong2*)&qT[d*132 + ty*8 + 4];  // (4,5),(6,7)
            float4 kf = *(const float4*)&kT[d*68 + tx*4];
            unsigned long long k0 = pack2(kf.x, kf.x);
            unsigned long long k1 = pack2(kf.y, kf.y);
            unsigned long long k2 = pack2(kf.z, kf.z);
            unsigned long long k3 = pack2(kf.w, kf.w);
            fma2(s2[0][0], qa.x, k0);  fma2(s2[0][1], qa.x, k1);
            fma2(s2[0][2], qa.x, k2);  fma2(s2[0][3], qa.x, k3);
            fma2(s2[1][0], qa.y, k0);  fma2(s2[1][1], qa.y, k1);
            fma2(s2[1][2], qa.y, k2);  fma2(s2[1][3], qa.y, k3);
            fma2(s2[2][0], qb2.x, k0); fma2(s2[2][1], qb2.x, k1);
            fma2(s2[2][2], qb2.x, k2); fma2(s2[2][3], qb2.x, k3);
            fma2(s2[3][0], qb2.y, k0); fma2(s2[3][1], qb2.y, k1);
            fma2(s2[3][2], qb2.y, k2); fma2(s2[3][3], qb2.y, k3);
        }

        // ---- softmax (online) ----
        float sc[8][4];
        #pragma unroll
        for (int a = 0; a < 4; a++)
            #pragma unroll
            for (int j = 0; j < 4; j++)
                unpack2(s2[a][j], sc[2*a][j], sc[2*a+1][j]);

        bool needmask = (kt >= 2*qt);
        float corr[8];
        #pragma unroll
        for (int ii = 0; ii < 8; ii++) {
            int ig = q0 + ty*8 + ii;
            float tm = -1e30f;
            #pragma unroll
            for (int jj = 0; jj < 4; jj++) {
                float v = sc[ii][jj]*0.125f;
                if (needmask && (j0 + tx*4 + jj > ig)) v = -1e30f;
                sc[ii][jj] = v;
                tm = fmaxf(tm, v);
            }
            tm = fmaxf(tm, __shfl_xor_sync(0xffffffffu, tm, 1));
            tm = fmaxf(tm, __shfl_xor_sync(0xffffffffu, tm, 2));
            tm = fmaxf(tm, __shfl_xor_sync(0xffffffffu, tm, 4));
            tm = fmaxf(tm, __shfl_xor_sync(0xffffffffu, tm, 8));
            float nm = fmaxf(m_i[ii], tm);
            corr[ii] = __expf(m_i[ii] - nm);
            m_i[ii] = nm;
            float ts = 0.f;
            #pragma unroll
            for (int jj = 0; jj < 4; jj++) {
                float p = __expf(sc[ii][jj] - nm);
                sc[ii][jj] = p; ts += p;
            }
            ts += __shfl_xor_sync(0xffffffffu, ts, 1);
            ts += __shfl_xor_sync(0xffffffffu, ts, 2);
            ts += __shfl_xor_sync(0xffffffffu, ts, 4);
            ts += __shfl_xor_sync(0xffffffffu, ts, 8);
            l_i[ii] = l_i[ii]*corr[ii] + ts;
        }
        // rescale O accumulators (packed row-pairs)
        #pragma unroll
        for (int a = 0; a < 4; a++) {
            unsigned long long c2 = pack2(corr[2*a], corr[2*a+1]);
            #pragma unroll
            for (int d = 0; d < 4; d++) o2[a][d] = mul2(o2[a][d], c2);
        }
        // store P transposed: psT[j][i]
        #pragma unroll
        for (int jj = 0; jj < 4; jj++)
            #pragma unroll
            for (int ii = 0; ii < 8; ii++)
                psT[(tx*4+jj)*132 + ty*8 + ii] = sc[ii][jj];
        __syncthreads();

        // ---- O += P @ V : reduce over j ----
        #pragma unroll 4
        for (int j = 0; j < 64; j++) {
            ulonglong2 pa = *(const ulonglong2*)&psT[j*132 + ty*8];
            ulonglong2 pb = *(const ulonglong2*)&psT[j*132 + ty*8 + 4];
            float4 vf = *(const float4*)&vs[j*68 + tx*4];
            unsigned long long v0 = pack2(vf.x, vf.x);
            unsigned long long v1 = pack2(vf.y, vf.y);
            unsigned long long v2 = pack2(vf.z, vf.z);
            unsigned long long v3 = pack2(vf.w, vf.w);
            fma2(o2[0][0], pa.x, v0);  fma2(o2[0][1], pa.x, v1);
            fma2(o2[0][2], pa.x, v2);  fma2(o2[0][3], pa.x, v3);
            fma2(o2[1][0], pa.y, v0);  fma2(o2[1][1], pa.y, v1);
            fma2(o2[1][2], pa.y, v2);  fma2(o2[1][3], pa.y, v3);
            fma2(o2[2][0], pb.x, v0);  fma2(o2[2][1], pb.x, v1);
            fma2(o2[2][2], pb.x, v2);  fma2(o2[2][3], pb.x, v3);
            fma2(o2[3][0], pb.y, v0);  fma2(o2[3][1], pb.y, v1);
            fma2(o2[3][2], pb.y, v2);  fma2(o2[3][3], pb.y, v3);
        }
    }

    // ---- epilogue ----
    float* Ob = O + (size_t)(b*SEQ + q0)*DMODEL + h*HD;
    #pragma unroll
    for (int a = 0; a < 4; a++) {
        float lo[4], hi[4];
        #pragma unroll
        for (int d = 0; d < 4; d++) unpack2(o2[a][d], lo[d], hi[d]);
        float inv0 = 1.f / l_i[2*a];
        float inv1 = 1.f / l_i[2*a+1];
        float4 f0, f1;
        f0.x = lo[0]*inv0; f0.y = lo[1]*inv0; f0.z = lo[2]*inv0; f0.w = lo[3]*inv0;
        f1.x = hi[0]*inv1; f1.y = hi[1]*inv1; f1.z = hi[2]*inv1; f1.w = hi[3]*inv1;
        *(float4*)&Ob[(size_t)(ty*8 + 2*a    )*DMODEL + tx*4] = f0;
        *(float4*)&Ob[(size_t)(ty*8 + 2*a + 1)*DMODEL + tx*4] = f1;
    }
}

// ---------------- launch ----------------
extern "C" void kernel_launch(void* const* d_in, const int* in_sizes, int n_in,
                              void* d_out, int out_size) {
    const float* x   = (const float*)d_in[0];
    const float* cs  = (const float*)d_in[1];
    const float* sn  = (const float*)d_in[2];
    const float* wq  = (const float*)d_in[3];
    const float* wk  = (const float*)d_in[4];
    const float* wv  = (const float*)d_in[5];
    const float* wo  = (const float*)d_in[6];
    const float* gq  = (const float*)d_in[7];
    const float* gk  = (const float*)d_in[8];
    const float* gv  = (const float*)d_in[9];
    const float* go  = (const float*)d_in[10];
    float* out = (float*)d_out;

    signed char *wq_q, *wk_q, *wv_q, *wo_q, *xq0, *xq1, *xq2, *xqo;
    float *xs0, *xs1, *xs2, *xso, *projq, *projk, *projv, *attnb;
    cudaGetSymbolAddress((void**)&wq_q, g_wq);
    cudaGetSymbolAddress((void**)&wk_q, g_wk);
    cudaGetSymbolAddress((void**)&wv_q, g_wv);
    cudaGetSymbolAddress((void**)&wo_q, g_wo);
    cudaGetSymbolAddress((void**)&xq0, g_xq0);
    cudaGetSymbolAddress((void**)&xq1, g_xq1);
    cudaGetSymbolAddress((void**)&xq2, g_xq2);
    cudaGetSymbolAddress((void**)&xqo, g_xqo);
    cudaGetSymbolAddress((void**)&xs0, g_xs0);
    cudaGetSymbolAddress((void**)&xs1, g_xs1);
    cudaGetSymbolAddress((void**)&xs2, g_xs2);
    cudaGetSymbolAddress((void**)&xso, g_xso);
    cudaGetSymbolAddress((void**)&projq, g_projq);
    cudaGetSymbolAddress((void**)&projk, g_projk);
    cudaGetSymbolAddress((void**)&projv, g_projv);
    cudaGetSymbolAddress((void**)&attnb, g_attn);

    cudaFuncSetAttribute(attn_kernel, cudaFuncAttributeMaxDynamicSharedMemorySize, 102400);

    // weight scales + ternary quant
    absum_partial<<<256, 256>>>(wq, DMODEL*DMODEL, 0);
    absum_partial<<<256, 256>>>(wk, NKV*HD*DMODEL, 1);
    absum_partial<<<256, 256>>>(wv, NKV*HD*DMODEL, 2);
    absum_partial<<<256, 256>>>(wo, DMODEL*DMODEL, 3);
    finalize_wscale<<<1, 256>>>();
    quant_w<<<2048, 256>>>(wq, wq_q, DMODEL*DMODEL, 0);
    quant_w<<<512, 256>>>(wk, wk_q, NKV*HD*DMODEL, 1);
    quant_w<<<512, 256>>>(wv, wv_q, NKV*HD*DMODEL, 2);
    quant_w<<<2048, 256>>>(wo, wo_q, DMODEL*DMODEL, 3);

    // activation quant (3 projections share x row + rmsnorm stat)
    act_quant<<<NTOK, 256>>>(x, gq, gk, gv, xq0, xq1, xq2, xs0, xs1, xs2);

    // projections
    gemm_i8<<<dim3(DMODEL/64, NTOK/128), 256>>>(xq0, wq_q, xs0, 0, projq, DMODEL);
    gemm_i8<<<dim3((NKV*HD)/64, NTOK/128), 256>>>(xq1, wk_q, xs1, 1, projk, NKV*HD);
    gemm_i8<<<dim3((NKV*HD)/64, NTOK/128), 256>>>(xq2, wv_q, xs2, 2, projv, NKV*HD);

    // rope
    rope_kernel<<<(NTOK*NH*32)/256, 256>>>(projq, cs, sn, NH);
    rope_kernel<<<(NTOK*NKV*32)/256, 256>>>(projk, cs, sn, NKV);

    // attention
    attn_kernel<<<dim3(SEQ/128, NH, BATCH), 256, 102400>>>(projq, projk, projv, attnb);

    // output bitlinear
    act_quant<<<NTOK, 256>>>(attnb, go, nullptr, nullptr, xqo, nullptr, nullptr, xso, nullptr, nullptr);
    gemm_i8<<<dim3(DMODEL/64, NTOK/128), 256>>>(xqo, wo_q, xso, 3, out, DMODEL);
}

// round 3
// speedup vs baseline: 2.8796x; 1.0101x over previous
#include <cuda_runtime.h>
#include <cuda_bf16.h>
#include <cstdint>

// Problem constants (fixed shapes)
#define BATCH 2
#define SEQ   2048
#define DMODEL 2048
#define NH    32
#define NKV   8
#define HD    64
#define NTOK  (BATCH*SEQ)          // 4096

// ---------------- f32x2 packed math helpers ----------------
__device__ __forceinline__ void fma2(unsigned long long &d, unsigned long long a, unsigned long long b) {
    asm("fma.rn.f32x2 %0, %1, %2, %0;" : "+l"(d) : "l"(a), "l"(b));
}
__device__ __forceinline__ unsigned long long mul2(unsigned long long a, unsigned long long b) {
    unsigned long long r;
    asm("mul.rn.f32x2 %0, %1, %2;" : "=l"(r) : "l"(a), "l"(b));
    return r;
}
__device__ __forceinline__ unsigned long long pack2(float lo, float hi) {
    unsigned long long r;
    asm("mov.b64 %0, {%1, %2};" : "=l"(r) : "f"(lo), "f"(hi));
    return r;
}
__device__ __forceinline__ void unpack2(unsigned long long v, float &lo, float &hi) {
    asm("mov.b64 {%0, %1}, %2;" : "=f"(lo), "=f"(hi) : "l"(v));
}

// ---------------- mma.sync / ldmatrix helpers ----------------
__device__ __forceinline__ void ldsm4(uint32_t &r0, uint32_t &r1, uint32_t &r2, uint32_t &r3, uint32_t addr) {
    asm volatile("ldmatrix.sync.aligned.m8n8.x4.shared.b16 {%0,%1,%2,%3}, [%4];"
                 : "=r"(r0), "=r"(r1), "=r"(r2), "=r"(r3) : "r"(addr));
}
__device__ __forceinline__ void imma16832(int* c, const uint32_t* a, const uint32_t* b) {
    asm volatile("mma.sync.aligned.m16n8k32.row.col.s32.s8.s8.s32 "
                 "{%0,%1,%2,%3}, {%4,%5,%6,%7}, {%8,%9}, {%0,%1,%2,%3};"
                 : "+r"(c[0]), "+r"(c[1]), "+r"(c[2]), "+r"(c[3])
                 : "r"(a[0]), "r"(a[1]), "r"(a[2]), "r"(a[3]), "r"(b[0]), "r"(b[1]));
}

// ---------------- device scratch (static, allocation-free) ----------------
__device__ float g_partial[4*256];
__device__ float g_wscale[4];
__device__ __align__(16) signed char g_wq[DMODEL*DMODEL];
__device__ __align__(16) signed char g_wk[NKV*HD*DMODEL];
__device__ __align__(16) signed char g_wv[NKV*HD*DMODEL];
__device__ __align__(16) signed char g_wo[DMODEL*DMODEL];
__device__ __align__(16) signed char g_xq0[NTOK*DMODEL];
__device__ __align__(16) signed char g_xq1[NTOK*DMODEL];
__device__ __align__(16) signed char g_xq2[NTOK*DMODEL];
__device__ __align__(16) signed char g_xqo[NTOK*DMODEL];
__device__ float g_xs0[NTOK];
__device__ float g_xs1[NTOK];
__device__ float g_xs2[NTOK];
__device__ float g_xso[NTOK];
__device__ float g_projq[NTOK*DMODEL];     // [token, h*64+d]
__device__ float g_projk[NTOK*NKV*HD];     // [token, kv*64+d]
__device__ float g_projv[NTOK*NKV*HD];
__device__ float g_attn[NTOK*DMODEL];      // [token, h*64+d]

// ---------------- weight abs-mean (deterministic 2-pass) ----------------
__global__ void absum_partial(const float* __restrict__ w, int n, int k) {
    __shared__ float red[256];
    int tid = threadIdx.x;
    float s = 0.f;
    for (int i = blockIdx.x*256 + tid; i < n; i += 256*256) s += fabsf(w[i]);
    red[tid] = s; __syncthreads();
    for (int st = 128; st > 0; st >>= 1) { if (tid < st) red[tid] += red[tid+st]; __syncthreads(); }
    if (tid == 0) g_partial[k*256 + blockIdx.x] = red[0];
}

__global__ void finalize_wscale() {
    __shared__ float red[256];
    int tid = threadIdx.x;
    const float ninv[4] = {1.f/(2048.f*2048.f), 1.f/(512.f*2048.f),
                           1.f/(512.f*2048.f), 1.f/(2048.f*2048.f)};
    for (int k = 0; k < 4; k++) {
        red[tid] = g_partial[k*256 + tid]; __syncthreads();
        for (int st = 128; st > 0; st >>= 1) { if (tid < st) red[tid] += red[tid+st]; __syncthreads(); }
        if (tid == 0) g_wscale[k] = fmaxf(red[0]*ninv[k], 1e-5f);
        __syncthreads();
    }
}

__global__ void quant_w(const float* __restrict__ w, signed char* __restrict__ wq, int n, int widx) {
    float inv = 1.f / g_wscale[widx];
    for (int i = blockIdx.x*blockDim.x + threadIdx.x; i < n; i += gridDim.x*blockDim.x) {
        float q = rintf(w[i]*inv);
        q = fminf(fmaxf(q, -1.f), 1.f);
        wq[i] = (signed char)q;
    }
}

// ---------------- activation quant (rmsnorm + absmax int8), up to 3 g's ----------------
__global__ void act_quant(const float* __restrict__ x,
                          const float* g0, const float* g1, const float* g2,
                          signed char* xq0, signed char* xq1, signed char* xq2,
                          float* s0, float* s1, float* s2) {
    __shared__ float xr[DMODEL];
    __shared__ float red[256];
    int row = blockIdx.x, tid = threadIdx.x;
    const float* xp = x + (size_t)row*DMODEL;
    float ss = 0.f;
    #pragma unroll
    for (int l = 0; l < 8; l++) { float v = xp[tid + l*256]; xr[tid + l*256] = v; ss += v*v; }
    red[tid] = ss; __syncthreads();
    for (int st = 128; st > 0; st >>= 1) { if (tid < st) red[tid] += red[tid+st]; __syncthreads(); }
    float rinv = rsqrtf(red[0]*(1.f/(float)DMODEL) + 1e-6f);
    __syncthreads();

    const float* gs[3] = {g0, g1, g2};
    signed char* xqs[3] = {xq0, xq1, xq2};
    float* scs[3] = {s0, s1, s2};
    for (int vI = 0; vI < 3; vI++) {
        const float* g = gs[vI];
        if (!g) continue;
        float amax = 0.f, xn[8];
        #pragma unroll
        for (int l = 0; l < 8; l++) {
            int i = tid + l*256;
            float v = xr[i]*rinv*g[i];
            xn[l] = v; amax = fmaxf(amax, fabsf(v));
        }
        red[tid] = amax; __syncthreads();
        for (int st = 128; st > 0; st >>= 1) { if (tid < st) red[tid] = fmaxf(red[tid], red[tid+st]); __syncthreads(); }
        float sc = fmaxf(red[0], 1e-5f);
        __syncthreads();
        float qf = 127.f/sc;
        #pragma unroll
        for (int l = 0; l < 8; l++) {
            int i = tid + l*256;
            float q = rintf(xn[l]*qf);
            q = fminf(fmaxf(q, -128.f), 127.f);
            xqs[vI][(size_t)row*DMODEL + i] = (signed char)q;
        }
        if (tid == 0) scs[vI][row] = sc;
    }
}

// ---------------- int8 tensor-core GEMM via mma.sync.m16n8k32 ----------------
// C[M,N] = A[M,K=2048] * B[N,K]^T, A/B int8 row-major (K contiguous).
// CTA tile 128x128, 8 warps (2 m x 4 n), warp tile 64x32, K-chunk 128B, SW128 smem.
__global__ __launch_bounds__(256)
void gemm_imma(const signed char* __restrict__ A, const signed char* __restrict__ B,
               const float* __restrict__ xsc, int widx,
               float* __restrict__ C, int N) {
    __shared__ alignas(16) int4 As4[128*8];
    __shared__ alignas(16) int4 Bs4[128*8];
    const int K = 2048;
    int tid = threadIdx.x;
    int lane = tid & 31, warp = tid >> 5;
    int warp_m = warp >> 2, warp_n = warp & 3;     // 2 x 4
    int m0 = blockIdx.y*128, n0 = blockIdx.x*128;

    uint32_t asb = (uint32_t)__cvta_generic_to_shared(As4);
    uint32_t bsb = (uint32_t)__cvta_generic_to_shared(Bs4);

    // per-lane ldmatrix addressing pieces
    int g = lane >> 3, lr = lane & 7;
    // A frag rows: warp_m*64 + mt*16 + (g&1)*8 + lr ; col16 = kk*2 + (g>>1)
    // B frag rows: warp_n*32 + nt2*16 + (g>>1)*8 + lr ; col16 = kk*2 + (g&1)
    int rowA_base = warp_m*64 + (g&1)*8 + lr;
    int rowB_base = warp_n*32 + (g>>1)*8 + lr;
    int acolg = g >> 1, bcolg = g & 1;

    // global load mapping: thread covers (row = tid/8 + l*32, 16B col = tid%8)
    int grow = tid >> 3, gcol = tid & 7;

    int c[4][4][4];
    #pragma unroll
    for (int mt = 0; mt < 4; mt++)
        #pragma unroll
        for (int nt = 0; nt < 4; nt++)
            #pragma unroll
            for (int i = 0; i < 4; i++) c[mt][nt][i] = 0;

    for (int kb = 0; kb < K/128; kb++) {
        __syncthreads();
        #pragma unroll
        for (int l = 0; l < 4; l++) {
            int row = grow + l*32;
            const int4* ag = (const int4*)(A + (size_t)(m0 + row)*K + kb*128 + gcol*16);
            As4[row*8 + (gcol ^ (row & 7))] = *ag;
            const int4* bg = (const int4*)(B + (size_t)(n0 + row)*K + kb*128 + gcol*16);
            Bs4[row*8 + (gcol ^ (row & 7))] = *bg;
        }
        __syncthreads();
        #pragma unroll
        for (int kk = 0; kk < 4; kk++) {
            uint32_t a[4][4];
            #pragma unroll
            for (int mt = 0; mt < 4; mt++) {
                int rowA = rowA_base + mt*16;
                uint32_t addr = asb + (uint32_t)(rowA*128 + (((kk*2 + acolg) ^ lr) << 4));
                ldsm4(a[mt][0], a[mt][1], a[mt][2], a[mt][3], addr);
            }
            uint32_t bfr[4][2];
            #pragma unroll
            for (int nt2 = 0; nt2 < 2; nt2++) {
                int rowB = rowB_base + nt2*16;
                uint32_t addr = bsb + (uint32_t)(rowB*128 + (((kk*2 + bcolg) ^ lr) << 4));
                uint32_t r0, r1, r2, r3;
                ldsm4(r0, r1, r2, r3, addr);
                bfr[nt2*2][0] = r0;   bfr[nt2*2][1] = r1;
                bfr[nt2*2+1][0] = r2; bfr[nt2*2+1][1] = r3;
            }
            #pragma unroll
            for (int mt = 0; mt < 4; mt++)
                #pragma unroll
                for (int nt = 0; nt < 4; nt++)
                    imma16832(c[mt][nt], a[mt], bfr[nt]);
        }
    }

    // epilogue: scale + store
    float wsc = g_wscale[widx] * (1.f/127.f);
    int lane4 = lane >> 2, lanec = (lane & 3)*2;
    #pragma unroll
    for (int mt = 0; mt < 4; mt++) {
        int r0 = m0 + warp_m*64 + mt*16 + lane4;
        float s0 = wsc * xsc[r0];
        float s1 = wsc * xsc[r0 + 8];
        #pragma unroll
        for (int nt = 0; nt < 4; nt++) {
            int col = n0 + warp_n*32 + nt*8 + lanec;
            float2 v0, v1;
            v0.x = c[mt][nt][0]*s0; v0.y = c[mt][nt][1]*s0;
            v1.x = c[mt][nt][2]*s1; v1.y = c[mt][nt][3]*s1;
            *(float2*)&C[(size_t)r0*N + col] = v0;
            *(float2*)&C[(size_t)(r0+8)*N + col] = v1;
        }
    }
}

// ---------------- RoPE (in place), layout [token, h*64+d] ----------------
__global__ void rope_kernel(float* __restrict__ buf, const float* __restrict__ cs,
                            const float* __restrict__ sn, int nh) {
    int idx = blockIdx.x*blockDim.x + threadIdx.x;   // over NTOK*nh*32
    int i = idx & 31;
    int h = (idx >> 5) % nh;
    int tok = (idx >> 5) / nh;
    int t = tok & (SEQ - 1);
    float* p = buf + (size_t)tok*(nh*HD) + h*HD;
    float c0 = cs[t*HD + i],      s0 = sn[t*HD + i];
    float c1 = cs[t*HD + 32 + i], s1 = sn[t*HD + 32 + i];
    float a = p[i], b = p[32 + i];
    p[i]      = a*c0 - b*s0;
    p[32 + i] = b*c1 + a*s1;
}

// ---------------- causal flash attention, GQA (n_rep=4), f32x2 register-tiled ----------------
// grid (SEQ/128, NH, B); 256 threads; dyn smem = 102400 B; 2 CTA/SM
__global__ __launch_bounds__(256, 2)
void attn_kernel(const float* __restrict__ Q, const float* __restrict__ K,
                 const float* __restrict__ V, float* __restrict__ O) {
    extern __shared__ float sm[];
    float* qT  = sm;                   // [64][132]  d-major: qT[d][i], i 0..127
    float* kT  = sm + 64*132;          // [64][68]   d-major: kT[d][j], j 0..63
    float* vs  = kT + 64*68;           // [64][68]   row-major: vs[j][d]
    float* psT = vs + 64*68;           // [64][132]  j-major: psT[j][i]
    int tid = threadIdx.x;
    int qt = blockIdx.x, h = blockIdx.y, b = blockIdx.z;
    int q0 = qt*128, kvh = h >> 2;
    int tx = tid & 15, ty = tid >> 4;
    const float* Qb = Q + (size_t)(b*SEQ + q0)*DMODEL + h*HD;
    const float* Kb = K + (size_t)(b*SEQ)*(NKV*HD) + kvh*HD;
    const float* Vb = V + (size_t)(b*SEQ)*(NKV*HD) + kvh*HD;

    // load Q tile transposed (128 rows x 64 d -> qT[d][i])
    #pragma unroll
    for (int l = 0; l < 8; l++) {
        int idx = tid + l*256;            // 0..2047
        int r = idx >> 4, c4 = idx & 15;
        float4 f = *(const float4*)&Qb[(size_t)r*DMODEL + c4*4];
        qT[(c4*4+0)*132 + r] = f.x;
        qT[(c4*4+1)*132 + r] = f.y;
        qT[(c4*4+2)*132 + r] = f.z;
        qT[(c4*4+3)*132 + r] = f.w;
    }

    float m_i[8], l_i[8];
    unsigned long long o2[4][4];          // [row-pair][dd], rows (ty*8+2a, ty*8+2a+1)
    #pragma unroll
    for (int i = 0; i < 8; i++) { m_i[i] = -1e30f; l_i[i] = 0.f; }
    #pragma unroll
    for (int a = 0; a < 4; a++)
        #pragma unroll
        for (int d = 0; d < 4; d++) o2[a][d] = 0ull;

    int ktmax = 2*qt + 1;
    for (int kt = 0; kt <= ktmax; kt++) {
        int j0 = kt*64;
        __syncthreads();   // previous PV done before overwriting kT/vs
        // load K transposed + V straight (64 x 64 each)
        #pragma unroll
        for (int l = 0; l < 4; l++) {
            int idx = tid + l*256;        // 0..1023
            int r = idx >> 4, c4 = idx & 15;
            float4 f = *(const float4*)&Kb[(size_t)(j0 + r)*(NKV*HD) + c4*4];
            kT[(c4*4+0)*68 + r] = f.x;
            kT[(c4*4+1)*68 + r] = f.y;
            kT[(c4*4+2)*68 + r] = f.z;
            kT[(c4*4+3)*68 + r] = f.w;
            float4 g = *(const float4*)&Vb[(size_t)(j0 + r)*(NKV*HD) + c4*4];
            *(float4*)&vs[r*68 + c4*4] = g;
        }
        __syncthreads();

        // ---- S = Q @ K^T : s2[row-pair a][jj] over d ----
        unsigned long long s2[4][4];
        #pragma unroll
        for (int a = 0; a < 4; a++)
            #pragma unroll
            for (int j = 0; j < 4; j++) s2[a][j] = 0ull;

        #pragma unroll 4
        for (int d = 0; d < 64; d++) {
            ulonglong2 qa = *(const ulonglong2*)&qT[d*132 + ty*8];       // row pairs (0,1),(2,3)
            ulonglong2 qb2 = *(const ulonglong2*)&qT[d*132 + ty*8 + 4];  // (4,5),(6,7)
            float4 kf = *(const float4*)&kT[d*68 + tx*4];
            unsigned long long k0 = pack2(kf.x, kf.x);
            unsigned long long k1 = pack2(kf.y, kf.y);
            unsigned long long k2 = pack2(kf.z, kf.z);
            unsigned long long k3 = pack2(kf.w, kf.w);
            fma2(s2[0][0], qa.x, k0);  fma2(s2[0][1], qa.x, k1);
            fma2(s2[0][2], qa.x, k2);  fma2(s2[0][3], qa.x, k3);
            fma2(s2[1][0], qa.y, k0);  fma2(s2[1][1], qa.y, k1);
            fma2(s2[1][2], qa.y, k2);  fma2(s2[1][3], qa.y, k3);
            fma2(s2[2][0], qb2.x, k0); fma2(s2[2][1], qb2.x, k1);
            fma2(s2[2][2], qb2.x, k2); fma2(s2[2][3], qb2.x, k3);
            fma2(s2[3][0], qb2.y, k0); fma2(s2[3][1], qb2.y, k1);
            fma2(s2[3][2], qb2.y, k2); fma2(s2[3][3], qb2.y, k3);
        }

        // ---- softmax (online) ----
        float sc[8][4];
        #pragma unroll
        for (int a = 0; a < 4; a++)
            #pragma unroll
            for (int j = 0; j < 4; j++)
                unpack2(s2[a][j], sc[2*a][j], sc[2*a+1][j]);

        bool needmask = (kt >= 2*qt);
        float corr[8];
        #pragma unroll
        for (int ii = 0; ii < 8; ii++) {
            int ig = q0 + ty*8 + ii;
            float tm = -1e30f;
            #pragma unroll
            for (int jj = 0; jj < 4; jj++) {
                float v = sc[ii][jj]*0.125f;
                if (needmask && (j0 + tx*4 + jj > ig)) v = -1e30f;
                sc[ii][jj] = v;
                tm = fmaxf(tm, v);
            }
            tm = fmaxf(tm, __shfl_xor_sync(0xffffffffu, tm, 1));
            tm = fmaxf(tm, __shfl_xor_sync(0xffffffffu, tm, 2));
            tm = fmaxf(tm, __shfl_xor_sync(0xffffffffu, tm, 4));
            tm = fmaxf(tm, __shfl_xor_sync(0xffffffffu, tm, 8));
            float nm = fmaxf(m_i[ii], tm);
            corr[ii] = __expf(m_i[ii] - nm);
            m_i[ii] = nm;
            float ts = 0.f;
            #pragma unroll
            for (int jj = 0; jj < 4; jj++) {
                float p = __expf(sc[ii][jj] - nm);
                sc[ii][jj] = p; ts += p;
            }
            ts += __shfl_xor_sync(0xffffffffu, ts, 1);
            ts += __shfl_xor_sync(0xffffffffu, ts, 2);
            ts += __shfl_xor_sync(0xffffffffu, ts, 4);
            ts += __shfl_xor_sync(0xffffffffu, ts, 8);
            l_i[ii] = l_i[ii]*corr[ii] + ts;
        }
        // rescale O accumulators (packed row-pairs)
        #pragma unroll
        for (int a = 0; a < 4; a++) {
            unsigned long long c2 = pack2(corr[2*a], corr[2*a+1]);
            #pragma unroll
            for (int d = 0; d < 4; d++) o2[a][d] = mul2(o2[a][d], c2);
        }
        // store P transposed: psT[j][i]
        #pragma unroll
        for (int jj = 0; jj < 4; jj++)
            #pragma unroll
            for (int ii = 0; ii < 8; ii++)
                psT[(tx*4+jj)*132 + ty*8 + ii] = sc[ii][jj];
        __syncthreads();

        // ---- O += P @ V : reduce over j ----
        #pragma unroll 4
        for (int j = 0; j < 64; j++) {
            ulonglong2 pa = *(const ulonglong2*)&psT[j*132 + ty*8];
            ulonglong2 pb = *(const ulonglong2*)&psT[j*132 + ty*8 + 4];
            float4 vf = *(const float4*)&vs[j*68 + tx*4];
            unsigned long long v0 = pack2(vf.x, vf.x);
            unsigned long long v1 = pack2(vf.y, vf.y);
            unsigned long long v2 = pack2(vf.z, vf.z);
            unsigned long long v3 = pack2(vf.w, vf.w);
            fma2(o2[0][0], pa.x, v0);  fma2(o2[0][1], pa.x, v1);
            fma2(o2[0][2], pa.x, v2);  fma2(o2[0][3], pa.x, v3);
            fma2(o2[1][0], pa.y, v0);  fma2(o2[1][1], pa.y, v1);
            fma2(o2[1][2], pa.y, v2);  fma2(o2[1][3], pa.y, v3);
            fma2(o2[2][0], pb.x, v0);  fma2(o2[2][1], pb.x, v1);
            fma2(o2[2][2], pb.x, v2);  fma2(o2[2][3], pb.x, v3);
            fma2(o2[3][0], pb.y, v0);  fma2(o2[3][1], pb.y, v1);
            fma2(o2[3][2], pb.y, v2);  fma2(o2[3][3], pb.y, v3);
        }
    }

    // ---- epilogue ----
    float* Ob = O + (size_t)(b*SEQ + q0)*DMODEL + h*HD;
    #pragma unroll
    for (int a = 0; a < 4; a++) {
        float lo[4], hi[4];
        #pragma unroll
        for (int d = 0; d < 4; d++) unpack2(o2[a][d], lo[d], hi[d]);
        float inv0 = 1.f / l_i[2*a];
        float inv1 = 1.f / l_i[2*a+1];
        float4 f0, f1;
        f0.x = lo[0]*inv0; f0.y = lo[1]*inv0; f0.z = lo[2]*inv0; f0.w = lo[3]*inv0;
        f1.x = hi[0]*inv1; f1.y = hi[1]*inv1; f1.z = hi[2]*inv1; f1.w = hi[3]*inv1;
        *(float4*)&Ob[(size_t)(ty*8 + 2*a    )*DMODEL + tx*4] = f0;
        *(float4*)&Ob[(size_t)(ty*8 + 2*a + 1)*DMODEL + tx*4] = f1;
    }
}

// ---------------- launch ----------------
extern "C" void kernel_launch(void* const* d_in, const int* in_sizes, int n_in,
                              void* d_out, int out_size) {
    const float* x   = (const float*)d_in[0];
    const float* cs  = (const float*)d_in[1];
    const float* sn  = (const float*)d_in[2];
    const float* wq  = (const float*)d_in[3];
    const float* wk  = (const float*)d_in[4];
    const float* wv  = (const float*)d_in[5];
    const float* wo  = (const float*)d_in[6];
    const float* gq  = (const float*)d_in[7];
    const float* gk  = (const float*)d_in[8];
    const float* gv  = (const float*)d_in[9];
    const float* go  = (const float*)d_in[10];
    float* out = (float*)d_out;

    signed char *wq_q, *wk_q, *wv_q, *wo_q, *xq0, *xq1, *xq2, *xqo;
    float *xs0, *xs1, *xs2, *xso, *projq, *projk, *projv, *attnb;
    cudaGetSymbolAddress((void**)&wq_q, g_wq);
    cudaGetSymbolAddress((void**)&wk_q, g_wk);
    cudaGetSymbolAddress((void**)&wv_q, g_wv);
    cudaGetSymbolAddress((void**)&wo_q, g_wo);
    cudaGetSymbolAddress((void**)&xq0, g_xq0);
    cudaGetSymbolAddress((void**)&xq1, g_xq1);
    cudaGetSymbolAddress((void**)&xq2, g_xq2);
    cudaGetSymbolAddress((void**)&xqo, g_xqo);
    cudaGetSymbolAddress((void**)&xs0, g_xs0);
    cudaGetSymbolAddress((void**)&xs1, g_xs1);
    cudaGetSymbolAddress((void**)&xs2, g_xs2);
    cudaGetSymbolAddress((void**)&xso, g_xso);
    cudaGetSymbolAddress((void**)&projq, g_projq);
    cudaGetSymbolAddress((void**)&projk, g_projk);
    cudaGetSymbolAddress((void**)&projv, g_projv);
    cudaGetSymbolAddress((void**)&attnb, g_attn);

    cudaFuncSetAttribute(attn_kernel, cudaFuncAttributeMaxDynamicSharedMemorySize, 102400);

    // weight scales + ternary quant
    absum_partial<<<256, 256>>>(wq, DMODEL*DMODEL, 0);
    absum_partial<<<256, 256>>>(wk, NKV*HD*DMODEL, 1);
    absum_partial<<<256, 256>>>(wv, NKV*HD*DMODEL, 2);
    absum_partial<<<256, 256>>>(wo, DMODEL*DMODEL, 3);
    finalize_wscale<<<1, 256>>>();
    quant_w<<<2048, 256>>>(wq, wq_q, DMODEL*DMODEL, 0);
    quant_w<<<512, 256>>>(wk, wk_q, NKV*HD*DMODEL, 1);
    quant_w<<<512, 256>>>(wv, wv_q, NKV*HD*DMODEL, 2);
    quant_w<<<2048, 256>>>(wo, wo_q, DMODEL*DMODEL, 3);

    // activation quant (3 projections share x row + rmsnorm stat)
    act_quant<<<NTOK, 256>>>(x, gq, gk, gv, xq0, xq1, xq2, xs0, xs1, xs2);

    // projections (tensor-core int8)
    gemm_imma<<<dim3(DMODEL/128, NTOK/128), 256>>>(xq0, wq_q, xs0, 0, projq, DMODEL);
    gemm_imma<<<dim3((NKV*HD)/128, NTOK/128), 256>>>(xq1, wk_q, xs1, 1, projk, NKV*HD);
    gemm_imma<<<dim3((NKV*HD)/128, NTOK/128), 256>>>(xq2, wv_q, xs2, 2, projv, NKV*HD);

    // rope
    rope_kernel<<<(NTOK*NH*32)/256, 256>>>(projq, cs, sn, NH);
    rope_kernel<<<(NTOK*NKV*32)/256, 256>>>(projk, cs, sn, NKV);

    // attention
    attn_kernel<<<dim3(SEQ/128, NH, BATCH), 256, 102400>>>(projq, projk, projv, attnb);

    // output bitlinear
    act_quant<<<NTOK, 256>>>(attnb, go, nullptr, nullptr, xqo, nullptr, nullptr, xso, nullptr, nullptr);
    gemm_imma<<<dim3(DMODEL/128, NTOK/128), 256>>>(xqo, wo_q, xso, 3, out, DMODEL);
}